// round 2
// baseline (speedup 1.0000x reference)
#include <cuda_runtime.h>
#include <cuda_bf16.h>

// Problem: B=32768, N=16, F=65. Rows = B*N = 524288.
// Per row: x = row[1..64], h = row[0].
//   gi = W_ih @ x          (3 dots of length 64)
//   gh = W_hh * h
//   r = sigmoid(gi0+gh0); z = sigmoid(gi1+gh1); n = tanh(gi2 + r*gh2)
//   h' = (1-z)*n + z*h ;  out = h'*w_out + b_out
//
// Strategy: one warp per row. Lane l loads row[1+l] and row[33+l]
// (coalesced), 6 cached weight loads, 3 FMAs, 3-value butterfly reduce,
// lane 0 finishes the gates. HBM-streaming bound (~138 MB total traffic).

#define ROWS_TOTAL 524288
#define ROW_STRIDE 65

__global__ __launch_bounds__(256) void gru_fused_kernel(
    const float* __restrict__ in,      // [ROWS_TOTAL, 65]
    const float* __restrict__ W_ih,    // [3, 64] row-major
    const float* __restrict__ W_hh,    // [3, 1]
    const float* __restrict__ b_ih,    // [3]
    const float* __restrict__ b_hh,    // [3]
    const float* __restrict__ w_out,   // [1,1]
    const float* __restrict__ b_out,   // [1]
    float* __restrict__ out)           // [ROWS_TOTAL]
{
    const int warp_global = (blockIdx.x * blockDim.x + threadIdx.x) >> 5;
    const int lane = threadIdx.x & 31;
    if (warp_global >= ROWS_TOTAL) return;

    const float* __restrict__ row = in + (long long)warp_global * ROW_STRIDE;

    // Coalesced row loads: lanes cover elements [1..32] and [33..64].
    const float x0 = row[1 + lane];
    const float x1 = row[33 + lane];
    // Hidden state: issue early (lane 0's value is the one used) so it
    // overlaps the reduction instead of serializing after it.
    const float h = row[0];

    // Weight loads hit L1/L2 after first wave (192 floats total).
    const float w0a = W_ih[lane];        const float w0b = W_ih[32 + lane];
    const float w1a = W_ih[64 + lane];   const float w1b = W_ih[96 + lane];
    const float w2a = W_ih[128 + lane];  const float w2b = W_ih[160 + lane];

    float s0 = fmaf(x0, w0a, x1 * w0b);
    float s1 = fmaf(x0, w1a, x1 * w1b);
    float s2 = fmaf(x0, w2a, x1 * w2b);

    #pragma unroll
    for (int off = 16; off > 0; off >>= 1) {
        s0 += __shfl_xor_sync(0xFFFFFFFFu, s0, off);
        s1 += __shfl_xor_sync(0xFFFFFFFFu, s1, off);
        s2 += __shfl_xor_sync(0xFFFFFFFFu, s2, off);
    }

    if (lane == 0) {
        const float gi0 = s0 + b_ih[0];
        const float gi1 = s1 + b_ih[1];
        const float gi2 = s2 + b_ih[2];
        const float gh0 = fmaf(h, W_hh[0], b_hh[0]);
        const float gh1 = fmaf(h, W_hh[1], b_hh[1]);
        const float gh2 = fmaf(h, W_hh[2], b_hh[2]);

        const float r = 1.0f / (1.0f + expf(-(gi0 + gh0)));
        const float z = 1.0f / (1.0f + expf(-(gi1 + gh1)));
        const float n = tanhf(fmaf(r, gh2, gi2));
        const float h_new = fmaf(z, h - n, n);   // (1-z)*n + z*h

        out[warp_global] = fmaf(h_new, w_out[0], b_out[0]);
    }
}

extern "C" void kernel_launch(void* const* d_in, const int* in_sizes, int n_in,
                              void* d_out, int out_size) {
    const float* inputs = (const float*)d_in[0];
    const float* W_ih   = (const float*)d_in[1];
    const float* W_hh   = (const float*)d_in[2];
    const float* b_ih   = (const float*)d_in[3];
    const float* b_hh   = (const float*)d_in[4];
    const float* w_out  = (const float*)d_in[5];
    const float* b_out  = (const float*)d_in[6];
    float* out = (float*)d_out;

    const int threads = 256;                       // 8 warps = 8 rows / block
    const int blocks = ROWS_TOTAL / (threads / 32); // 65536
    gru_fused_kernel<<<blocks, threads>>>(inputs, W_ih, W_hh, b_ih, b_hh,
                                          w_out, b_out, out);
}

// round 3
// speedup vs baseline: 3.3612x; 3.3612x over previous
#include <cuda_runtime.h>
#include <cstdint>

// Problem: 524288 rows of 65 fp32 (h = row[0], x = row[1..64]).
// One GRU cell + Linear(1,1) per row.
//
// Round-3 design: thread-per-row.
//   - cp.async.bulk stages 128 rows (33,280 B) per block into smem (1 instr).
//   - thread t computes row t: 64 scalar LDS (stride 65 -> conflict-free,
//     since 65 mod 32 == 1), weights as float4 smem broadcasts.
//   - gate math with all lanes active (32 rows/warp), zero shuffles.

#define ROWS_TOTAL   524288
#define ROW_F        65
#define THREADS      128
#define ROWS_PER_BLK 128
#define TILE_FLOATS  (ROWS_PER_BLK * ROW_F)       // 8320
#define TILE_BYTES   (TILE_FLOATS * 4)            // 33280 (16B multiple)

__device__ __forceinline__ uint32_t smem_u32(const void* p) {
    return (uint32_t)__cvta_generic_to_shared(p);
}

__global__ __launch_bounds__(THREADS) void gru_tpr_kernel(
    const float* __restrict__ in,      // [ROWS_TOTAL, 65]
    const float* __restrict__ W_ih,    // [3, 64]
    const float* __restrict__ W_hh,    // [3]
    const float* __restrict__ b_ih,    // [3]
    const float* __restrict__ b_hh,    // [3]
    const float* __restrict__ w_out,   // [1]
    const float* __restrict__ b_out,   // [1]
    float* __restrict__ out)           // [ROWS_TOTAL]
{
    __shared__ __align__(16) float sx[TILE_FLOATS];   // 33,280 B row tile
    __shared__ __align__(16) float sw[192];           // W_ih
    __shared__ __align__(8)  uint64_t mbar;

    const int tid = threadIdx.x;
    const uint32_t mbar_a = smem_u32(&mbar);

    if (tid == 0) {
        asm volatile("mbarrier.init.shared.b64 [%0], %1;"
                     :: "r"(mbar_a), "r"(1) : "memory");
    }
    // Stage weights (48 float4 = 192 floats) while barrier init settles.
    if (tid < 48) {
        ((float4*)sw)[tid] = ((const float4*)W_ih)[tid];
    }
    __syncthreads();   // mbarrier visible to async proxy; sw staged

    if (tid == 0) {
        const float* src = in + (size_t)blockIdx.x * TILE_FLOATS;
        asm volatile("mbarrier.arrive.expect_tx.shared.b64 _, [%0], %1;"
                     :: "r"(mbar_a), "r"((uint32_t)TILE_BYTES) : "memory");
        asm volatile(
            "cp.async.bulk.shared::cta.global.mbarrier::complete_tx::bytes "
            "[%0], [%1], %2, [%3];"
            :: "r"(smem_u32(sx)), "l"(src), "r"((uint32_t)TILE_BYTES),
               "r"(mbar_a) : "memory");
    }

    // Small uniform params (L1-cached broadcast loads), overlap the TMA.
    const float bi0 = b_ih[0],  bi1 = b_ih[1],  bi2 = b_ih[2];
    const float wh0 = W_hh[0],  wh1 = W_hh[1],  wh2 = W_hh[2];
    const float bh0 = b_hh[0],  bh1 = b_hh[1],  bh2 = b_hh[2];
    const float wo  = w_out[0], bo  = b_out[0];

    // Wait for the bulk copy (parity 0; kernel body runs once).
    {
        asm volatile(
            "{\n\t"
            ".reg .pred p;\n\t"
            "W%=:\n\t"
            "mbarrier.try_wait.parity.acquire.cta.shared::cta.b64 p, [%0], 0;\n\t"
            "@!p bra W%=;\n\t"
            "}"
            :: "r"(mbar_a) : "memory");
    }

    // ---- compute: thread t owns row t ----
    const float* __restrict__ xr = sx + tid * ROW_F;   // conflict-free stride
    const float h = xr[0];

    float s0 = 0.f, s1 = 0.f, s2 = 0.f;
    const float4* __restrict__ swq = (const float4*)sw;
    #pragma unroll
    for (int c = 0; c < 16; ++c) {
        const float4 w0 = swq[c];
        const float4 w1 = swq[16 + c];
        const float4 w2 = swq[32 + c];
        const float a0 = xr[1 + 4 * c + 0];
        const float a1 = xr[1 + 4 * c + 1];
        const float a2 = xr[1 + 4 * c + 2];
        const float a3 = xr[1 + 4 * c + 3];
        s0 = fmaf(a0, w0.x, fmaf(a1, w0.y, fmaf(a2, w0.z, fmaf(a3, w0.w, s0))));
        s1 = fmaf(a0, w1.x, fmaf(a1, w1.y, fmaf(a2, w1.z, fmaf(a3, w1.w, s1))));
        s2 = fmaf(a0, w2.x, fmaf(a1, w2.y, fmaf(a2, w2.z, fmaf(a3, w2.w, s2))));
    }

    const float gi0 = s0 + bi0;
    const float gi1 = s1 + bi1;
    const float gi2 = s2 + bi2;
    const float gh0 = fmaf(h, wh0, bh0);
    const float gh1 = fmaf(h, wh1, bh1);
    const float gh2 = fmaf(h, wh2, bh2);

    const float r = 1.0f / (1.0f + expf(-(gi0 + gh0)));
    const float z = 1.0f / (1.0f + expf(-(gi1 + gh1)));
    const float n = tanhf(fmaf(r, gh2, gi2));
    const float h_new = fmaf(z, h - n, n);   // (1-z)*n + z*h

    out[blockIdx.x * ROWS_PER_BLK + tid] = fmaf(h_new, wo, bo);
}

extern "C" void kernel_launch(void* const* d_in, const int* in_sizes, int n_in,
                              void* d_out, int out_size) {
    const float* inputs = (const float*)d_in[0];
    const float* W_ih   = (const float*)d_in[1];
    const float* W_hh   = (const float*)d_in[2];
    const float* b_ih   = (const float*)d_in[3];
    const float* b_hh   = (const float*)d_in[4];
    const float* w_out  = (const float*)d_in[5];
    const float* b_out  = (const float*)d_in[6];
    float* out = (float*)d_out;

    const int blocks = ROWS_TOTAL / ROWS_PER_BLK;   // 4096
    gru_tpr_kernel<<<blocks, THREADS>>>(inputs, W_ih, W_hh, b_ih, b_hh,
                                        w_out, b_out, out);
}

// round 4
// speedup vs baseline: 3.3650x; 1.0011x over previous
#include <cuda_runtime.h>
#include <cstdint>

// 524288 rows x 65 fp32 (h = row[0], x = row[1..64]); GRU cell + Linear(1,1).
//
// Round-4: persistent CTAs, double-buffered cp.async.bulk.
//   grid = 444 (148 SMs x 3 CTAs @ ~67 KB smem), each CTA strides over
//   4096 tiles of 128 rows, prefetching tile i+1 while computing tile i.
//   Thread-per-row compute from smem (stride-65 = conflict-free banks).

#define ROWS_TOTAL   524288
#define ROW_F        65
#define THREADS      128
#define ROWS_PER_TILE 128
#define NTILES       (ROWS_TOTAL / ROWS_PER_TILE)   // 4096
#define TILE_FLOATS  (ROWS_PER_TILE * ROW_F)        // 8320
#define TILE_BYTES   (TILE_FLOATS * 4)              // 33280
#define GRID_CTAS    444                            // 148 * 3
#define DYN_SMEM_BYTES ((2 * TILE_FLOATS + 192) * 4) // 67328

__device__ __forceinline__ uint32_t smem_u32(const void* p) {
    return (uint32_t)__cvta_generic_to_shared(p);
}

__device__ __forceinline__ void mbar_wait(uint32_t mbar_a, uint32_t parity) {
    asm volatile(
        "{\n\t"
        ".reg .pred p;\n\t"
        "W%=:\n\t"
        "mbarrier.try_wait.parity.acquire.cta.shared::cta.b64 p, [%0], %1;\n\t"
        "@!p bra W%=;\n\t"
        "}"
        :: "r"(mbar_a), "r"(parity) : "memory");
}

__device__ __forceinline__ void issue_bulk(uint32_t dst_smem, const float* src,
                                           uint32_t mbar_a) {
    asm volatile("mbarrier.arrive.expect_tx.shared.b64 _, [%0], %1;"
                 :: "r"(mbar_a), "r"((uint32_t)TILE_BYTES) : "memory");
    asm volatile(
        "cp.async.bulk.shared::cta.global.mbarrier::complete_tx::bytes "
        "[%0], [%1], %2, [%3];"
        :: "r"(dst_smem), "l"(src), "r"((uint32_t)TILE_BYTES), "r"(mbar_a)
        : "memory");
}

__global__ __launch_bounds__(THREADS) void gru_persist_kernel(
    const float* __restrict__ in,      // [ROWS_TOTAL, 65]
    const float* __restrict__ W_ih,    // [3, 64]
    const float* __restrict__ W_hh,    // [3]
    const float* __restrict__ b_ih,    // [3]
    const float* __restrict__ b_hh,    // [3]
    const float* __restrict__ w_out,   // [1]
    const float* __restrict__ b_out,   // [1]
    float* __restrict__ out)           // [ROWS_TOTAL]
{
    extern __shared__ __align__(16) float sdyn[];
    float* const buf0 = sdyn;
    float* const buf1 = sdyn + TILE_FLOATS;
    float* const sw   = sdyn + 2 * TILE_FLOATS;   // 192 floats W_ih
    __shared__ __align__(8) uint64_t mbar[2];

    const int tid = threadIdx.x;
    const uint32_t mb0 = smem_u32(&mbar[0]);
    const uint32_t mb1 = smem_u32(&mbar[1]);

    if (tid < 2) {
        asm volatile("mbarrier.init.shared.b64 [%0], %1;"
                     :: "r"(tid ? mb1 : mb0), "r"(1) : "memory");
    }
    if (tid < 48) ((float4*)sw)[tid] = ((const float4*)W_ih)[tid];
    __syncthreads();   // mbarriers + weights visible

    // Prologue: prefetch first tile into buf0.
    if (tid == 0) {
        issue_bulk(smem_u32(buf0), in + (size_t)blockIdx.x * TILE_FLOATS, mb0);
    }

    // Uniform scalars (overlap the first copy).
    const float bi0 = b_ih[0],  bi1 = b_ih[1],  bi2 = b_ih[2];
    const float wh0 = W_hh[0],  wh1 = W_hh[1],  wh2 = W_hh[2];
    const float bh0 = b_hh[0],  bh1 = b_hh[1],  bh2 = b_hh[2];
    const float wo  = w_out[0], bo  = b_out[0];

    uint32_t ph[2] = {0u, 0u};
    int i = 0;
    for (int tile = blockIdx.x; tile < NTILES; tile += GRID_CTAS, ++i) {
        const int cur = i & 1;
        float* const bcur = cur ? buf1 : buf0;
        const uint32_t mb_cur = cur ? mb1 : mb0;
        const uint32_t mb_oth = cur ? mb0 : mb1;

        // All threads finished reading the other buffer (previous iter)
        // before we overwrite it with the next prefetch.
        __syncthreads();
        const int nxt = tile + GRID_CTAS;
        if (tid == 0 && nxt < NTILES) {
            float* const both = cur ? buf0 : buf1;
            issue_bulk(smem_u32(both), in + (size_t)nxt * TILE_FLOATS, mb_oth);
        }

        mbar_wait(mb_cur, ph[cur]);
        ph[cur] ^= 1u;

        // ---- compute: thread t owns row t of this tile ----
        const float* __restrict__ xr = bcur + tid * ROW_F;
        const float h = xr[0];

        float s0 = 0.f, s1 = 0.f, s2 = 0.f;
        const float4* __restrict__ swq = (const float4*)sw;
        #pragma unroll
        for (int c = 0; c < 16; ++c) {
            const float4 w0 = swq[c];
            const float4 w1 = swq[16 + c];
            const float4 w2 = swq[32 + c];
            const float a0 = xr[1 + 4 * c + 0];
            const float a1 = xr[1 + 4 * c + 1];
            const float a2 = xr[1 + 4 * c + 2];
            const float a3 = xr[1 + 4 * c + 3];
            s0 = fmaf(a0, w0.x, fmaf(a1, w0.y, fmaf(a2, w0.z, fmaf(a3, w0.w, s0))));
            s1 = fmaf(a0, w1.x, fmaf(a1, w1.y, fmaf(a2, w1.z, fmaf(a3, w1.w, s1))));
            s2 = fmaf(a0, w2.x, fmaf(a1, w2.y, fmaf(a2, w2.z, fmaf(a3, w2.w, s2))));
        }

        const float gi0 = s0 + bi0;
        const float gi1 = s1 + bi1;
        const float gi2 = s2 + bi2;
        const float gh0 = fmaf(h, wh0, bh0);
        const float gh1 = fmaf(h, wh1, bh1);
        const float gh2 = fmaf(h, wh2, bh2);

        const float r = 1.0f / (1.0f + expf(-(gi0 + gh0)));
        const float z = 1.0f / (1.0f + expf(-(gi1 + gh1)));
        const float n = tanhf(fmaf(r, gh2, gi2));
        const float h_new = fmaf(z, h - n, n);   // (1-z)*n + z*h

        out[tile * ROWS_PER_TILE + tid] = fmaf(h_new, wo, bo);
    }
}

extern "C" void kernel_launch(void* const* d_in, const int* in_sizes, int n_in,
                              void* d_out, int out_size) {
    const float* inputs = (const float*)d_in[0];
    const float* W_ih   = (const float*)d_in[1];
    const float* W_hh   = (const float*)d_in[2];
    const float* b_ih   = (const float*)d_in[3];
    const float* b_hh   = (const float*)d_in[4];
    const float* w_out  = (const float*)d_in[5];
    const float* b_out  = (const float*)d_in[6];
    float* out = (float*)d_out;

    cudaFuncSetAttribute(gru_persist_kernel,
                         cudaFuncAttributeMaxDynamicSharedMemorySize,
                         DYN_SMEM_BYTES);
    gru_persist_kernel<<<GRID_CTAS, THREADS, DYN_SMEM_BYTES>>>(
        inputs, W_ih, W_hh, b_ih, b_hh, w_out, b_out, out);
}